// round 15
// baseline (speedup 1.0000x reference)
#include <cuda_runtime.h>

#define D_ 768
#define B_ 64
#define A_ 256
#define L_ 2
#define NG1 4
#define NG2 8
#define BHW 704
#define NS1 4              // stage1 split-K  (K=192)
#define NS2 6              // M2 split-K      (K=128)
#define NH1 (NG1 * B_ * D_)
#define NM2 (A_ * L_ * D_)

// ---- scratch (.bss device globals; 16B-aligned for vector access) ----
__device__ __align__(16) float g_h1p[NS1][NG1 * B_ * D_];
__device__ __align__(16) float g_h1[NG1 * B_ * D_];
__device__ __align__(16) float g_Bh[D_ * BHW];            // Wh packed by g2-bin
__device__ __align__(16) float g_M2p[NS2][A_ * L_ * D_];  // M2 split-K partials
__device__ __align__(16) float g_M2[A_ * L_ * D_];        // summed M2 [a][l][d]
__device__ __align__(16) float g_c[A_ * L_];
__device__ int   g_slot2a[NG2 * A_];
__device__ int   g_off2[NG2], g_cnt2[NG2];
__device__ int   g_slot1a[NG1 * A_];           // g1-bin slot -> annotator
__device__ int   g_cnt1[NG1];

__device__ __forceinline__ void ffma2(unsigned long long& acc,
                                      unsigned long long a,
                                      unsigned long long b) {
    asm("fma.rn.f32x2 %0, %1, %2, %0;" : "+l"(acc) : "l"(a), "l"(b));
}
__device__ __forceinline__ unsigned long long pack2(float lo, float hi) {
    unsigned long long r;
    asm("mov.b64 %0, {%1, %2};" : "=l"(r) : "f"(lo), "f"(hi));
    return r;
}
__device__ __forceinline__ void unpack2(unsigned long long v, float& lo, float& hi) {
    asm("mov.b64 {%0, %1}, %2;" : "=f"(lo), "=f"(hi) : "l"(v));
}

// ---------------------------------------------------------------------------
// Gather + inline prep (g2 bins for M2, g1 bins for heads).
// Grid (NG2, 12 e-tiles); y==0 blocks publish the bin globals.
// ---------------------------------------------------------------------------
__global__ void __launch_bounds__(256) gather_kernel(const float* __restrict__ Wh,
                                                     const int* __restrict__ g1i,
                                                     const int* __restrict__ g2i) {
    const int g  = blockIdx.x;
    const int e0 = blockIdx.y * 64;
    const int t  = threadIdx.x;

    __shared__ int sg1[A_], sg2[A_];
    __shared__ int scnt[NG2];
    __shared__ int slist[A_];          // slot -> annotator for g2-bin g
    __shared__ int slist1[A_];         // slot -> annotator for g1-bin g (g<4)
    __shared__ int s_off, s_cnt, s_cnt1;
    __shared__ __align__(16) float stile[64][98];

    sg1[t] = g1i[t];
    sg2[t] = g2i[t];
    __syncthreads();
    {
        const int m2 = sg2[t];
        int slot2 = 0;
        for (int i = 0; i < t; i++) slot2 += (sg2[i] == m2);
        if (m2 == g) slist[slot2] = t;
        if (g < NG1) {
            const int m1 = sg1[t];
            int slot1 = 0;
            for (int i = 0; i < t; i++) slot1 += (sg1[i] == m1);
            if (m1 == g) slist1[slot1] = t;
        }
        if (t < NG2) {
            int c = 0;
            for (int i = 0; i < A_; i++) c += (sg2[i] == t);
            scnt[t] = c;
        }
    }
    __syncthreads();
    if (t == 0) {
        int o = 0;
        for (int j = 0; j < NG2; j++) {
            if (j == g) s_off = o;
            o += (2 * scnt[j] + 7) & ~7;
        }
        s_cnt = scnt[g];
        if (g < NG1) {
            int c = 0;
            for (int i = 0; i < A_; i++) c += (sg1[i] == g);
            s_cnt1 = c;
        }
    }
    __syncthreads();
    const int cnt = s_cnt;
    const int off = s_off;

    if (blockIdx.y == 0) {
        if (t < cnt) g_slot2a[g * A_ + t] = slist[t];
        if (t == 0) { g_off2[g] = off; g_cnt2[g] = cnt; }
        if (g < NG1) {
            if (t < s_cnt1) g_slot1a[g * A_ + t] = slist1[t];
            if (t == 0) g_cnt1[g] = s_cnt1;
        }
    }
    if (cnt == 0) return;

    const int warp = t >> 5, lane = t & 31;
    for (int sb = 0; sb < cnt; sb += 48) {
        const int nsl = min(48, cnt - sb);
        for (int s = warp; s < nsl; s += 8) {
            const int a = slist[sb + s];
            float4 v = *(const float4*)(Wh + a * (D_ * L_) + e0 * 2 + lane * 4);
            const int er = lane * 2;
            stile[er][2 * s]         = v.x;
            stile[er][2 * s + 1]     = v.y;
            stile[er + 1][2 * s]     = v.z;
            stile[er + 1][2 * s + 1] = v.w;
        }
        __syncthreads();
        const int w2 = nsl;
        for (int idx = t; idx < 64 * w2; idx += 256) {
            const int r = idx / w2, c2i = idx % w2;
            float2 v = *(const float2*)&stile[r][c2i * 2];
            *(float2*)(g_Bh + (e0 + r) * BHW + off + sb * 2 + c2i * 2) = v;
        }
        __syncthreads();
    }
}

// ---------------------------------------------------------------------------
// cbias: g_c[a][l] = b2[g2[a]] . Wh[a][:,l] + bh[a][l].
// ---------------------------------------------------------------------------
__global__ void __launch_bounds__(128) cbias_kernel(const float* __restrict__ b2,
                                                    const float* __restrict__ Wh,
                                                    const float* __restrict__ bh,
                                                    const int* __restrict__ g2i) {
    const int a = blockIdx.x;
    const int t = threadIdx.x;
    __shared__ float red[4][2];
    const int g2 = g2i[a];
    float s0 = 0.f, s1 = 0.f;
#pragma unroll
    for (int i = 0; i < 6; i++) {
        const int e = i * 128 + t;
        const float bv = b2[g2 * D_ + e];
        float2 wv = *(const float2*)(Wh + a * (D_ * L_) + 2 * e);
        s0 += bv * wv.x;
        s1 += bv * wv.y;
    }
#pragma unroll
    for (int o = 16; o; o >>= 1) {
        s0 += __shfl_down_sync(~0u, s0, o);
        s1 += __shfl_down_sync(~0u, s1, o);
    }
    const int warp = t >> 5, lane = t & 31;
    if (lane == 0) { red[warp][0] = s0; red[warp][1] = s1; }
    __syncthreads();
    if (t == 0) {
        g_c[a * 2 + 0] = red[0][0] + red[1][0] + red[2][0] + red[3][0] + bh[a * 2 + 0];
        g_c[a * 2 + 1] = red[0][1] + red[1][1] + red[2][1] + red[3][1] + bh[a * 2 + 1];
    }
}

// ---------------------------------------------------------------------------
// GEMM body (R11, unchanged — best measured).
// ---------------------------------------------------------------------------
template <int MR, int NC, int NCH>
__device__ __forceinline__ void gemm_t(const float* __restrict__ Ab, int lda,
                                       const float* __restrict__ Bb, int ldb,
                                       float* pool, int gid, int cl,
                                       unsigned long long acc[8][2]) {
    constexpr int WA = MR + 4;
    constexpr int WB = NC + 4;
    constexpr int NA = MR / 32;
    constexpr int NB = NC / 32;
    float (*AsT)[16][WA] = (float (*)[16][WA])pool;
    float (*Bs)[16][WB]  = (float (*)[16][WB])(pool + 2 * 16 * WA);

    const int t = threadIdx.x;
    const int ar  = t >> 2;
    const int akq = (t & 3) * 4;

    const float* aptr = Ab + ar * lda + akq;
    const float* bptr[NB];
    int bkr[NB], bcq[NB];
#pragma unroll
    for (int i = 0; i < NB; i++) {
        const int idx = i * 128 + t;
        bkr[i] = idx / (NC / 4);
        bcq[i] = (idx % (NC / 4)) * 4;
        bptr[i] = Bb + bkr[i] * ldb + bcq[i];
    }

#pragma unroll
    for (int p = 0; p < 8; p++) { acc[p][0] = 0ull; acc[p][1] = 0ull; }

    float4 pa[NA], pb[NB];
#pragma unroll
    for (int i = 0; i < NA; i++) pa[i] = *(const float4*)(aptr + i * 32 * lda);
#pragma unroll
    for (int i = 0; i < NB; i++) pb[i] = *(const float4*)(bptr[i]);
#pragma unroll
    for (int i = 0; i < NA; i++) {
        AsT[0][akq + 0][ar + i * 32] = pa[i].x;
        AsT[0][akq + 1][ar + i * 32] = pa[i].y;
        AsT[0][akq + 2][ar + i * 32] = pa[i].z;
        AsT[0][akq + 3][ar + i * 32] = pa[i].w;
    }
#pragma unroll
    for (int i = 0; i < NB; i++)
        *(float4*)&Bs[0][bkr[i]][bcq[i]] = pb[i];
    if (NCH > 1) {
#pragma unroll
        for (int i = 0; i < NA; i++)
            pa[i] = *(const float4*)(aptr + 16 + i * 32 * lda);
#pragma unroll
        for (int i = 0; i < NB; i++)
            pb[i] = *(const float4*)(bptr[i] + 16 * ldb);
    }
    __syncthreads();

#pragma unroll 1
    for (int c = 0; c < NCH; c++) {
        const int cur = c & 1;
        const int nxt = cur ^ 1;
        if (c + 1 < NCH) {
#pragma unroll
            for (int i = 0; i < NA; i++) {
                AsT[nxt][akq + 0][ar + i * 32] = pa[i].x;
                AsT[nxt][akq + 1][ar + i * 32] = pa[i].y;
                AsT[nxt][akq + 2][ar + i * 32] = pa[i].z;
                AsT[nxt][akq + 3][ar + i * 32] = pa[i].w;
            }
#pragma unroll
            for (int i = 0; i < NB; i++)
                *(float4*)&Bs[nxt][bkr[i]][bcq[i]] = pb[i];
        }
        if (c + 2 < NCH) {
#pragma unroll
            for (int i = 0; i < NA; i++)
                pa[i] = *(const float4*)(aptr + (c + 2) * 16 + i * 32 * lda);
#pragma unroll
            for (int i = 0; i < NB; i++)
                pb[i] = *(const float4*)(bptr[i] + (c + 2) * 16 * ldb);
        }
#pragma unroll
        for (int kk = 0; kk < 16; kk++) {
            float4 af0 = *(const float4*)&AsT[cur][kk][gid * 8];
            float4 af1 = *(const float4*)&AsT[cur][kk][gid * 8 + 4];
            ulonglong2 bp = *(const ulonglong2*)&Bs[cur][kk][cl];
            unsigned long long ad;
            ad = pack2(af0.x, af0.x); ffma2(acc[0][0], ad, bp.x); ffma2(acc[0][1], ad, bp.y);
            ad = pack2(af0.y, af0.y); ffma2(acc[1][0], ad, bp.x); ffma2(acc[1][1], ad, bp.y);
            ad = pack2(af0.z, af0.z); ffma2(acc[2][0], ad, bp.x); ffma2(acc[2][1], ad, bp.y);
            ad = pack2(af0.w, af0.w); ffma2(acc[3][0], ad, bp.x); ffma2(acc[3][1], ad, bp.y);
            ad = pack2(af1.x, af1.x); ffma2(acc[4][0], ad, bp.x); ffma2(acc[4][1], ad, bp.y);
            ad = pack2(af1.y, af1.y); ffma2(acc[5][0], ad, bp.x); ffma2(acc[5][1], ad, bp.y);
            ad = pack2(af1.z, af1.z); ffma2(acc[6][0], ad, bp.x); ffma2(acc[6][1], ad, bp.y);
            ad = pack2(af1.w, af1.w); ffma2(acc[7][0], ad, bp.x); ffma2(acc[7][1], ad, bp.y);
        }
        __syncthreads();
    }
}

// ---------------------------------------------------------------------------
// Fat GEMM (R11, unchanged): 128-thr blocks, 5 CTAs/SM, 768 blocks.
// ---------------------------------------------------------------------------
__global__ void __launch_bounds__(128, 5) fat_gemm(const float* __restrict__ pooled,
                                                   const float* __restrict__ W1,
                                                   const float* __restrict__ b1,
                                                   const float* __restrict__ W2) {
    __shared__ __align__(16) float pool[5376];
    unsigned long long acc[8][2];

    const int t = threadIdx.x;
    const int w = t >> 5, lane = t & 31;
    const int bx = blockIdx.x;

    if (bx < 192) {
        const int nt = bx % 6;
        const int mt = (bx / 6) & 1;
        const int g  = (bx / 12) & 3;
        const int s  = bx / 48;
        const int n0 = nt * 128;
        const int m0 = mt * 32;
        const int k0 = s * 192;
        gemm_t<32, 128, 12>(pooled + m0 * D_ + k0, D_,
                            W1 + g * D_ * D_ + k0 * D_ + n0, D_,
                            pool, w, lane * 4, acc);

        float* C = g_h1p[s] + g * B_ * D_;
        const int col = n0 + lane * 4;
        float4 bb = make_float4(0.f, 0.f, 0.f, 0.f);
        if (s == 0) bb = *(const float4*)(b1 + g * D_ + col);
#pragma unroll
        for (int j = 0; j < 8; j++) {
            float4 v;
            unpack2(acc[j][0], v.x, v.y);
            unpack2(acc[j][1], v.z, v.w);
            v.x += bb.x; v.y += bb.y; v.z += bb.z; v.w += bb.w;
            *(float4*)(C + (m0 + w * 8 + j) * D_ + col) = v;
        }
    } else {
        const int idx = bx - 192;
        const int g   = idx & 7;
        const int dt  = (idx >> 3) % 12;
        const int s   = idx / 96;
        const int ncols = 2 * g_cnt2[g];
        if (ncols == 0) return;
        const int d0 = dt * 64;
        const int k0 = s * 128;
        const int cbase = g_off2[g];
        const int gid = w * 2 + (lane >> 4);
        const int cl  = (lane & 15) * 4;

        for (int cb = 0; cb < ncols; cb += 64) {
            gemm_t<64, 64, 8>(W2 + g * D_ * D_ + d0 * D_ + k0, D_,
                              g_Bh + k0 * BHW + cbase + cb, BHW,
                              pool, gid, cl, acc);
            const int rowbase = d0 + gid * 8;
#pragma unroll
            for (int np = 0; np < 2; np++) {
                const int c = cb + cl + np * 2;
                if (c < ncols) {
                    const int a = g_slot2a[g * A_ + (c >> 1)];
                    float* o0 = g_M2p[s] + (a * 2 + 0) * D_ + rowbase;
                    float* o1 = g_M2p[s] + (a * 2 + 1) * D_ + rowbase;
                    float4 v0, v1;
                    unpack2(acc[0][np], v0.x, v1.x);
                    unpack2(acc[1][np], v0.y, v1.y);
                    unpack2(acc[2][np], v0.z, v1.z);
                    unpack2(acc[3][np], v0.w, v1.w);
                    *(float4*)(o0)     = v0;
                    *(float4*)(o1)     = v1;
                    unpack2(acc[4][np], v0.x, v1.x);
                    unpack2(acc[5][np], v0.y, v1.y);
                    unpack2(acc[6][np], v0.z, v1.z);
                    unpack2(acc[7][np], v0.w, v1.w);
                    *(float4*)(o0 + 4) = v0;
                    *(float4*)(o1 + 4) = v1;
                }
            }
            __syncthreads();
        }
    }
}

// ---------------------------------------------------------------------------
// Fused sum: g_h1 = sum h1p (4), g_M2 = sum M2p (6). 576 blocks, 1 f4/thread.
// ---------------------------------------------------------------------------
__global__ void __launch_bounds__(256) sum_kernel() {
    const int i = (blockIdx.x * 256 + threadIdx.x) * 4;
    if (i < NH1) {
        float4 v0 = *(const float4*)(g_h1p[0] + i);
        float4 v1 = *(const float4*)(g_h1p[1] + i);
        float4 v2 = *(const float4*)(g_h1p[2] + i);
        float4 v3 = *(const float4*)(g_h1p[3] + i);
        v0.x += v1.x + v2.x + v3.x;
        v0.y += v1.y + v2.y + v3.y;
        v0.z += v1.z + v2.z + v3.z;
        v0.w += v1.w + v2.w + v3.w;
        *(float4*)(g_h1 + i) = v0;
    } else {
        const int j = i - NH1;
        float4 v = *(const float4*)(g_M2p[0] + j);
#pragma unroll
        for (int s = 1; s < NS2; s++) {
            float4 u = *(const float4*)(g_M2p[s] + j);
            v.x += u.x; v.y += u.y; v.z += u.z; v.w += u.w;
        }
        *(float4*)(g_M2 + j) = v;
    }
}

// ---------------------------------------------------------------------------
// Heads as bin-blocked dot-GEMV. Grid 128 = 4 bins x 8 b-groups x 4 p-splits.
// 8 h1 rows staged in smem once, reused across all (a,l) pairs of the bin.
// Each warp streams one M2 row (global) against the 8 smem rows.
// ---------------------------------------------------------------------------
__global__ void __launch_bounds__(256) heads_kernel(float* __restrict__ out) {
    const int bx  = blockIdx.x;
    const int bin = bx & 3;
    const int bg  = (bx >> 2) & 7;
    const int ps  = bx >> 5;
    const int b0  = bg * 8;
    const int t   = threadIdx.x;
    const int warp = t >> 5, lane = t & 31;

    __shared__ __align__(16) float h1s[8][776];

    const float* hbin = g_h1 + bin * B_ * D_;
#pragma unroll
    for (int r = 0; r < 8; r++) {
        if (t < 192)
            *(float4*)&h1s[r][t * 4] = *(const float4*)(hbin + (b0 + r) * D_ + t * 4);
    }
    __syncthreads();

    const int npairs = 2 * g_cnt1[bin];

    for (int p = ps * 8 + warp; p < npairs; p += 32) {
        const int a = g_slot1a[bin * A_ + (p >> 1)];
        const int l = p & 1;
        const float* m2row = g_M2 + (a * 2 + l) * D_;
        float acc[8];
#pragma unroll
        for (int r = 0; r < 8; r++) acc[r] = 0.f;
#pragma unroll
        for (int i = 0; i < 6; i++) {
            const int dd = i * 128 + lane * 4;
            float4 m = *(const float4*)(m2row + dd);
#pragma unroll
            for (int r = 0; r < 8; r++) {
                float4 h = *(const float4*)&h1s[r][dd];
                acc[r] += m.x * h.x + m.y * h.y + m.z * h.z + m.w * h.w;
            }
        }
#pragma unroll
        for (int o = 16; o; o >>= 1) {
#pragma unroll
            for (int r = 0; r < 8; r++)
                acc[r] += __shfl_down_sync(~0u, acc[r], o);
        }
        if (lane == 0) {
            const float cb = g_c[a * 2 + l];
#pragma unroll
            for (int r = 0; r < 8; r++)
                out[((b0 + r) * A_ + a) * L_ + l] = acc[r] + cb;
        }
    }
}

extern "C" void kernel_launch(void* const* d_in, const int* in_sizes, int n_in,
                              void* d_out, int out_size) {
    const float* pooled = (const float*)d_in[0];
    const float* W1     = (const float*)d_in[1];
    const float* b1     = (const float*)d_in[2];
    const float* W2     = (const float*)d_in[3];
    const float* b2     = (const float*)d_in[4];
    const float* Wh     = (const float*)d_in[5];
    const float* bh     = (const float*)d_in[6];
    const int*   g1i    = (const int*)d_in[7];
    const int*   g2i    = (const int*)d_in[8];
    float* out = (float*)d_out;

    gather_kernel<<<dim3(NG2, 12), 256>>>(Wh, g1i, g2i);
    cbias_kernel<<<A_, 128>>>(b2, Wh, bh, g2i);
    fat_gemm<<<192 + NG2 * 12 * NS2, 128>>>(pooled, W1, b1, W2);
    sum_kernel<<<(NH1 + NM2) / 1024, 256>>>();
    heads_kernel<<<128, 256>>>(out);
}

// round 16
// speedup vs baseline: 1.1004x; 1.1004x over previous
#include <cuda_runtime.h>

#define D_ 768
#define B_ 64
#define A_ 256
#define L_ 2
#define NG1 4
#define NG2 8
#define BHW 704
#define NS1 3              // stage1 split-K  (K=256)
#define NS2 4              // M2 split-K      (K=192)
#define NH1 (NG1 * B_ * D_)

// ---- scratch (.bss device globals; 16B-aligned for vector access) ----
__device__ __align__(16) float g_h1p[NS1][NG1 * B_ * D_];
__device__ __align__(16) float g_h1[NG1 * B_ * D_];
__device__ __align__(16) float g_Bh[D_ * BHW];            // Wh packed by g2-bin
__device__ __align__(16) float g_M2p[NS2][A_ * L_ * D_];  // M2 split-K partials
__device__ int   g_slot2a[NG2 * A_];
__device__ int   g_off2[NG2], g_cnt2[NG2];

__device__ __forceinline__ void ffma2(unsigned long long& acc,
                                      unsigned long long a,
                                      unsigned long long b) {
    asm("fma.rn.f32x2 %0, %1, %2, %0;" : "+l"(acc) : "l"(a), "l"(b));
}
__device__ __forceinline__ unsigned long long pack2(float lo, float hi) {
    unsigned long long r;
    asm("mov.b64 %0, {%1, %2};" : "=l"(r) : "f"(lo), "f"(hi));
    return r;
}
__device__ __forceinline__ void unpack2(unsigned long long v, float& lo, float& hi) {
    asm("mov.b64 {%0, %1}, %2;" : "=f"(lo), "=f"(hi) : "l"(v));
}

// ---------------------------------------------------------------------------
// Gather + inline prep (R13-proven): grid (NG2, 12 e-tiles); y==0 publishes
// the g2-bin globals used by fat_gemm. Packs Wh into g_Bh[e][col].
// ---------------------------------------------------------------------------
__global__ void __launch_bounds__(256) gather_kernel(const float* __restrict__ Wh,
                                                     const int* __restrict__ g2i) {
    const int g  = blockIdx.x;
    const int e0 = blockIdx.y * 64;
    const int t  = threadIdx.x;

    __shared__ int sg[A_];
    __shared__ int scnt[NG2];
    __shared__ int slist[A_];
    __shared__ int s_off, s_cnt;
    __shared__ __align__(16) float stile[64][98];

    sg[t] = g2i[t];
    __syncthreads();
    {
        const int mg = sg[t];
        int slot = 0;
        for (int i = 0; i < t; i++) slot += (sg[i] == mg);
        if (mg == g) slist[slot] = t;
        if (t < NG2) {
            int c = 0;
            for (int i = 0; i < A_; i++) c += (sg[i] == t);
            scnt[t] = c;
        }
    }
    __syncthreads();
    if (t == 0) {
        int o = 0;
        for (int j = 0; j < NG2; j++) {
            if (j == g) s_off = o;
            o += (2 * scnt[j] + 7) & ~7;
        }
        s_cnt = scnt[g];
    }
    __syncthreads();
    const int cnt = s_cnt;
    const int off = s_off;

    if (blockIdx.y == 0) {
        if (t < cnt) g_slot2a[g * A_ + t] = slist[t];
        if (t == 0) { g_off2[g] = off; g_cnt2[g] = cnt; }
    }
    if (cnt == 0) return;

    const int warp = t >> 5, lane = t & 31;
    for (int sb = 0; sb < cnt; sb += 48) {
        const int nsl = min(48, cnt - sb);
        for (int s = warp; s < nsl; s += 8) {
            const int a = slist[sb + s];
            float4 v = *(const float4*)(Wh + a * (D_ * L_) + e0 * 2 + lane * 4);
            const int er = lane * 2;
            stile[er][2 * s]         = v.x;
            stile[er][2 * s + 1]     = v.y;
            stile[er + 1][2 * s]     = v.z;
            stile[er + 1][2 * s + 1] = v.w;
        }
        __syncthreads();
        const int w2 = nsl;
        for (int idx = t; idx < 64 * w2; idx += 256) {
            const int r = idx / w2, c2i = idx % w2;
            float2 v = *(const float2*)&stile[r][c2i * 2];
            *(float2*)(g_Bh + (e0 + r) * BHW + off + sb * 2 + c2i * 2) = v;
        }
        __syncthreads();
    }
}

// ---------------------------------------------------------------------------
// GEMM body (R9 exact): tile MR x NC x (16*NCH), 128 threads, double-buffered
// smem with store/sync ... compute/sync per chunk.
// Inner k-step: 2 broadcast LDS.128 (A) + 1 LDS.128 (B) + 8 pack2 + 16 ffma2.
// ---------------------------------------------------------------------------
template <int MR, int NC, int NCH>
__device__ __forceinline__ void gemm_t(const float* __restrict__ Ab, int lda,
                                       const float* __restrict__ Bb, int ldb,
                                       float* pool, int gid, int cl,
                                       unsigned long long acc[8][2]) {
    constexpr int WA = MR + 4;
    constexpr int WB = NC + 4;
    constexpr int NA = MR / 32;
    constexpr int NB = NC / 32;
    float (*AsT)[16][WA] = (float (*)[16][WA])pool;
    float (*Bs)[16][WB]  = (float (*)[16][WB])(pool + 2 * 16 * WA);

    const int t = threadIdx.x;
    const int ar  = t >> 2;
    const int akq = (t & 3) * 4;

    const float* aptr = Ab + ar * lda + akq;
    const float* bptr[NB];
    int bkr[NB], bcq[NB];
#pragma unroll
    for (int i = 0; i < NB; i++) {
        const int idx = i * 128 + t;
        bkr[i] = idx / (NC / 4);
        bcq[i] = (idx % (NC / 4)) * 4;
        bptr[i] = Bb + bkr[i] * ldb + bcq[i];
    }

#pragma unroll
    for (int p = 0; p < 8; p++) { acc[p][0] = 0ull; acc[p][1] = 0ull; }

    float4 pa[NA], pb[NB];
#pragma unroll
    for (int i = 0; i < NA; i++) pa[i] = *(const float4*)(aptr + i * 32 * lda);
#pragma unroll
    for (int i = 0; i < NB; i++) pb[i] = *(const float4*)(bptr[i]);

#pragma unroll 1
    for (int c = 0; c < NCH; c++) {
        const int cur = c & 1;
#pragma unroll
        for (int i = 0; i < NA; i++) {
            AsT[cur][akq + 0][ar + i * 32] = pa[i].x;
            AsT[cur][akq + 1][ar + i * 32] = pa[i].y;
            AsT[cur][akq + 2][ar + i * 32] = pa[i].z;
            AsT[cur][akq + 3][ar + i * 32] = pa[i].w;
        }
#pragma unroll
        for (int i = 0; i < NB; i++)
            *(float4*)&Bs[cur][bkr[i]][bcq[i]] = pb[i];
        __syncthreads();
        if (c + 1 < NCH) {
#pragma unroll
            for (int i = 0; i < NA; i++)
                pa[i] = *(const float4*)(aptr + (c + 1) * 16 + i * 32 * lda);
#pragma unroll
            for (int i = 0; i < NB; i++)
                pb[i] = *(const float4*)(bptr[i] + (c + 1) * 16 * ldb);
        }
#pragma unroll
        for (int kk = 0; kk < 16; kk++) {
            float4 af0 = *(const float4*)&AsT[cur][kk][gid * 8];
            float4 af1 = *(const float4*)&AsT[cur][kk][gid * 8 + 4];
            ulonglong2 bp = *(const ulonglong2*)&Bs[cur][kk][cl];
            unsigned long long ad;
            ad = pack2(af0.x, af0.x); ffma2(acc[0][0], ad, bp.x); ffma2(acc[0][1], ad, bp.y);
            ad = pack2(af0.y, af0.y); ffma2(acc[1][0], ad, bp.x); ffma2(acc[1][1], ad, bp.y);
            ad = pack2(af0.z, af0.z); ffma2(acc[2][0], ad, bp.x); ffma2(acc[2][1], ad, bp.y);
            ad = pack2(af0.w, af0.w); ffma2(acc[3][0], ad, bp.x); ffma2(acc[3][1], ad, bp.y);
            ad = pack2(af1.x, af1.x); ffma2(acc[4][0], ad, bp.x); ffma2(acc[4][1], ad, bp.y);
            ad = pack2(af1.y, af1.y); ffma2(acc[5][0], ad, bp.x); ffma2(acc[5][1], ad, bp.y);
            ad = pack2(af1.z, af1.z); ffma2(acc[6][0], ad, bp.x); ffma2(acc[6][1], ad, bp.y);
            ad = pack2(af1.w, af1.w); ffma2(acc[7][0], ad, bp.x); ffma2(acc[7][1], ad, bp.y);
        }
        __syncthreads();
    }
}

// ---------------------------------------------------------------------------
// Fat GEMM (R9 exact): 128-thr blocks, 4 CTAs/SM, 528 blocks:
//   [0,144):   stage1 32x128 tiles (6n x 2m x 4g x 3 splits, K=256)
//   [144,528): M2 64x64 tiles (8g x 12d x 4 splits, K=192)
// ---------------------------------------------------------------------------
__global__ void __launch_bounds__(128, 4) fat_gemm(const float* __restrict__ pooled,
                                                   const float* __restrict__ W1,
                                                   const float* __restrict__ b1,
                                                   const float* __restrict__ W2) {
    __shared__ __align__(16) float pool[5376];
    unsigned long long acc[8][2];

    const int t = threadIdx.x;
    const int w = t >> 5, lane = t & 31;
    const int bx = blockIdx.x;

    if (bx < 144) {
        const int nt = bx % 6;
        const int mt = (bx / 6) & 1;
        const int g  = (bx / 12) & 3;
        const int s  = bx / 48;
        const int n0 = nt * 128;
        const int m0 = mt * 32;
        const int k0 = s * 256;
        gemm_t<32, 128, 16>(pooled + m0 * D_ + k0, D_,
                            W1 + g * D_ * D_ + k0 * D_ + n0, D_,
                            pool, w, lane * 4, acc);

        float* C = g_h1p[s] + g * B_ * D_;
        const int col = n0 + lane * 4;
        float4 bb = make_float4(0.f, 0.f, 0.f, 0.f);
        if (s == 0) bb = *(const float4*)(b1 + g * D_ + col);
#pragma unroll
        for (int j = 0; j < 8; j++) {
            float4 v;
            unpack2(acc[j][0], v.x, v.y);
            unpack2(acc[j][1], v.z, v.w);
            v.x += bb.x; v.y += bb.y; v.z += bb.z; v.w += bb.w;
            *(float4*)(C + (m0 + w * 8 + j) * D_ + col) = v;
        }
    } else {
        const int idx = bx - 144;
        const int g   = idx & 7;
        const int dt  = (idx >> 3) % 12;
        const int s   = idx / 96;
        const int ncols = 2 * g_cnt2[g];
        if (ncols == 0) return;
        const int d0 = dt * 64;
        const int k0 = s * 192;
        const int cbase = g_off2[g];
        const int gid = w * 2 + (lane >> 4);
        const int cl  = (lane & 15) * 4;

        for (int cb = 0; cb < ncols; cb += 64) {
            gemm_t<64, 64, 12>(W2 + g * D_ * D_ + d0 * D_ + k0, D_,
                               g_Bh + k0 * BHW + cbase + cb, BHW,
                               pool, gid, cl, acc);
            const int rowbase = d0 + gid * 8;
#pragma unroll
            for (int np = 0; np < 2; np++) {
                const int c = cb + cl + np * 2;
                if (c < ncols) {
                    const int a = g_slot2a[g * A_ + (c >> 1)];
                    float* o0 = g_M2p[s] + (a * 2 + 0) * D_ + rowbase;
                    float* o1 = g_M2p[s] + (a * 2 + 1) * D_ + rowbase;
                    float4 v0, v1;
                    unpack2(acc[0][np], v0.x, v1.x);
                    unpack2(acc[1][np], v0.y, v1.y);
                    unpack2(acc[2][np], v0.z, v1.z);
                    unpack2(acc[3][np], v0.w, v1.w);
                    *(float4*)(o0)     = v0;
                    *(float4*)(o1)     = v1;
                    unpack2(acc[4][np], v0.x, v1.x);
                    unpack2(acc[5][np], v0.y, v1.y);
                    unpack2(acc[6][np], v0.z, v1.z);
                    unpack2(acc[7][np], v0.w, v1.w);
                    *(float4*)(o0 + 4) = v0;
                    *(float4*)(o1 + 4) = v1;
                }
            }
        }
    }
}

// ---------------------------------------------------------------------------
// Sum h1 partials (NS1=3): 192 blocks, 1 float4 per thread.
// ---------------------------------------------------------------------------
__global__ void __launch_bounds__(256) sumh1_kernel() {
    const int idx = (blockIdx.x * 256 + threadIdx.x) * 4;
    float4 v0 = *(const float4*)(g_h1p[0] + idx);
    float4 v1 = *(const float4*)(g_h1p[1] + idx);
    float4 v2 = *(const float4*)(g_h1p[2] + idx);
    v0.x += v1.x + v2.x;
    v0.y += v1.y + v2.y;
    v0.z += v1.z + v2.z;
    v0.w += v1.w + v2.w;
    *(float4*)(g_h1 + idx) = v0;
}

// ---------------------------------------------------------------------------
// Heads (R9 exact): out[b][a][l] = h1[g1[a]][b][:].M2[a][l][:] + cbias inline.
// M2 = sum of 4 split-K partials staged into smem.
// ---------------------------------------------------------------------------
__global__ void __launch_bounds__(256) heads_kernel(const float* __restrict__ b2,
                                                    const float* __restrict__ Wh,
                                                    const float* __restrict__ bh,
                                                    const int* __restrict__ g1i,
                                                    const int* __restrict__ g2i,
                                                    float* __restrict__ out) {
    const int a = blockIdx.x;
    const int t = threadIdx.x;
    __shared__ __align__(16) float m2s[L_ * D_];
    __shared__ float cred[8][2];
    __shared__ float cc[2];

#pragma unroll
    for (int i = 0; i < 2; i++) {
        const int f = (i * 256 + t) * 4;
        if (f < L_ * D_) {
            float4 v0 = *(const float4*)(g_M2p[0] + a * (L_ * D_) + f);
            float4 v1 = *(const float4*)(g_M2p[1] + a * (L_ * D_) + f);
            float4 v2 = *(const float4*)(g_M2p[2] + a * (L_ * D_) + f);
            float4 v3 = *(const float4*)(g_M2p[3] + a * (L_ * D_) + f);
            v0.x += v1.x + v2.x + v3.x;
            v0.y += v1.y + v2.y + v3.y;
            v0.z += v1.z + v2.z + v3.z;
            v0.w += v1.w + v2.w + v3.w;
            *(float4*)&m2s[f] = v0;
        }
    }

    // inline cbias: c[l] = b2[g2] . Wh[a][:,l] + bh[a][l]
    const int g2 = g2i[a];
    float s0 = 0.f, s1 = 0.f;
#pragma unroll
    for (int i = 0; i < 3; i++) {
        const int e = i * 256 + t;
        const float bv = b2[g2 * D_ + e];
        float2 wv = *(const float2*)(Wh + a * (D_ * L_) + 2 * e);
        s0 += bv * wv.x;
        s1 += bv * wv.y;
    }
#pragma unroll
    for (int o = 16; o; o >>= 1) {
        s0 += __shfl_down_sync(~0u, s0, o);
        s1 += __shfl_down_sync(~0u, s1, o);
    }
    const int warp = t >> 5, lane = t & 31;
    if (lane == 0) { cred[warp][0] = s0; cred[warp][1] = s1; }
    __syncthreads();
    if (t == 0) {
        float a0 = 0.f, a1 = 0.f;
#pragma unroll
        for (int ww = 0; ww < 8; ww++) { a0 += cred[ww][0]; a1 += cred[ww][1]; }
        cc[0] = a0 + bh[a * 2 + 0];
        cc[1] = a1 + bh[a * 2 + 1];
    }
    __syncthreads();

    const float c0 = cc[0], c1 = cc[1];
    const float* h = g_h1 + g1i[a] * B_ * D_;

    for (int b = warp; b < B_; b += 8) {
        const float* hb = h + b * D_;
        float r0 = 0.f, r1 = 0.f;
#pragma unroll
        for (int i = 0; i < 6; i++) {
            const int dd = i * 128 + lane * 4;
            float4 hv = *(const float4*)(hb + dd);
            float4 m0 = *(const float4*)&m2s[dd];
            float4 m1 = *(const float4*)&m2s[D_ + dd];
            r0 += hv.x * m0.x + hv.y * m0.y + hv.z * m0.z + hv.w * m0.w;
            r1 += hv.x * m1.x + hv.y * m1.y + hv.z * m1.z + hv.w * m1.w;
        }
#pragma unroll
        for (int o = 16; o; o >>= 1) {
            r0 += __shfl_down_sync(~0u, r0, o);
            r1 += __shfl_down_sync(~0u, r1, o);
        }
        if (lane == 0) {
            out[(b * A_ + a) * L_ + 0] = r0 + c0;
            out[(b * A_ + a) * L_ + 1] = r1 + c1;
        }
    }
}

extern "C" void kernel_launch(void* const* d_in, const int* in_sizes, int n_in,
                              void* d_out, int out_size) {
    const float* pooled = (const float*)d_in[0];
    const float* W1     = (const float*)d_in[1];
    const float* b1     = (const float*)d_in[2];
    const float* W2     = (const float*)d_in[3];
    const float* b2     = (const float*)d_in[4];
    const float* Wh     = (const float*)d_in[5];
    const float* bh     = (const float*)d_in[6];
    const int*   g1i    = (const int*)d_in[7];
    const int*   g2i    = (const int*)d_in[8];
    float* out = (float*)d_out;

    gather_kernel<<<dim3(NG2, 12), 256>>>(Wh, g2i);
    fat_gemm<<<144 + NG2 * 12 * NS2, 128>>>(pooled, W1, b1, W2);
    sumh1_kernel<<<192, 256>>>();
    heads_kernel<<<A_, 256>>>(b2, Wh, bh, g1i, g2i, out);
}